// round 5
// baseline (speedup 1.0000x reference)
#include <cuda_runtime.h>
#include <cuda_bf16.h>

// GNNLayer: out[b,n] = relu( (sum_{e: dst[e]==n} adj[e]*w[e]*x[b,src[e]]) * x[0,n]*self_w[n] + bias[n] )
// B=64, N=20000, E=1280000.
//
// Strategy:
//  1) transpose x [B,N] -> x_t [N,B] (contiguous 256B per node column) + zero acc
//  2) edge kernel: 16 lanes per edge, float4 gather from x_t, float4 atomicAdd
//     into acc [N,B] (x_t + acc = 10.2 MB, fully L2-resident on 126 MB L2)
//  3) finalize: tiled transpose acc [N,B] -> out [B,N] with scale+bias+relu

#define GNN_B 64
#define GNN_N 20000
#define GNN_E 1280000

__device__ float g_xt[GNN_N * GNN_B];    // x transposed [N, B]
__device__ float g_acc[GNN_N * GNN_B];   // accumulator  [N, B]

// ---------------------------------------------------------------------------
// Kernel 1: transpose x [B,N] -> g_xt [N,B], zero g_acc.
// 32x32 tiles, block (32,8). grid (N/32, B/32) = (625, 2).
// ---------------------------------------------------------------------------
__global__ void gnn_transpose_kernel(const float* __restrict__ x) {
    __shared__ float tile[32][33];
    const int n0 = blockIdx.x * 32;
    const int b0 = blockIdx.y * 32;
    const int tx = threadIdx.x;
    const int ty = threadIdx.y;

    #pragma unroll
    for (int i = ty; i < 32; i += 8) {
        // read x[b0+i][n0+tx] — coalesced along n
        tile[i][tx] = x[(b0 + i) * GNN_N + (n0 + tx)];
    }
    __syncthreads();
    #pragma unroll
    for (int i = ty; i < 32; i += 8) {
        // write x_t[n0+i][b0+tx] — coalesced along b
        const int idx = (n0 + i) * GNN_B + (b0 + tx);
        g_xt[idx]  = tile[tx][i];
        g_acc[idx] = 0.0f;
    }
}

// ---------------------------------------------------------------------------
// Kernel 2: per-edge scaled scatter-add.
// 16 threads per edge (2 edges per warp); each thread owns one float4
// (4 batch slots). Gather x_t[src] (contiguous 256B per edge), scale by
// adj*w, vector atomicAdd into acc[dst] (no return value -> RED in SASS).
// ---------------------------------------------------------------------------
__global__ void gnn_edge_kernel(const float* __restrict__ adj,
                                const float* __restrict__ w,
                                const int*   __restrict__ src,
                                const int*   __restrict__ dst,
                                int num_edges) {
    const int tid  = blockIdx.x * blockDim.x + threadIdx.x;
    const int e    = tid >> 4;        // edge index
    const int lane = tid & 15;        // 0..15, owns 4 floats of the 64-wide row
    if (e >= num_edges) return;

    const int   s = __ldg(&src[e]);
    const int   d = __ldg(&dst[e]);
    const float c = __ldg(&adj[e]) * __ldg(&w[e]);

    const float4 v = *reinterpret_cast<const float4*>(&g_xt[s * GNN_B + lane * 4]);
    const float4 r = make_float4(v.x * c, v.y * c, v.z * c, v.w * c);

    // sm_90+ vector atomic; result unused so ptxas emits RED.E.ADD.v4
    atomicAdd(reinterpret_cast<float4*>(&g_acc[d * GNN_B + lane * 4]), r);
}

// ---------------------------------------------------------------------------
// Kernel 3: finalize. acc [N,B] -> out [B,N] with per-n scale, bias, relu.
// self_loop[n] = x[0,n] * self_w[n].
// ---------------------------------------------------------------------------
__global__ void gnn_finalize_kernel(const float* __restrict__ x,
                                    const float* __restrict__ self_w,
                                    const float* __restrict__ bias,
                                    float* __restrict__ out) {
    __shared__ float tile[32][33];
    const int n0 = blockIdx.x * 32;
    const int b0 = blockIdx.y * 32;
    const int tx = threadIdx.x;
    const int ty = threadIdx.y;

    #pragma unroll
    for (int i = ty; i < 32; i += 8) {
        // read acc[n0+i][b0+tx] — coalesced along b
        tile[i][tx] = g_acc[(n0 + i) * GNN_B + (b0 + tx)];
    }
    __syncthreads();

    #pragma unroll
    for (int i = ty; i < 32; i += 8) {
        // write out[b0+i][n0+tx] — coalesced along n
        const int n  = n0 + tx;
        const float sl = x[n] * self_w[n];       // x row 0
        const float bb = bias[n];
        const float v  = tile[tx][i] * sl + bb;
        out[(b0 + i) * GNN_N + n] = fmaxf(v, 0.0f);
    }
}

extern "C" void kernel_launch(void* const* d_in, const int* in_sizes, int n_in,
                              void* d_out, int out_size) {
    const float* x      = (const float*)d_in[0];   // [B, N]
    const float* adj    = (const float*)d_in[1];   // [E]
    const float* w      = (const float*)d_in[2];   // [E]
    const float* self_w = (const float*)d_in[3];   // [N]
    const float* bias   = (const float*)d_in[4];   // [N]
    const int*   src    = (const int*)d_in[5];     // [E]
    const int*   dst    = (const int*)d_in[6];     // [E]
    float*       out    = (float*)d_out;           // [B, N]

    const int num_edges = in_sizes[1];             // E

    dim3 tb(32, 8);
    dim3 tg(GNN_N / 32, GNN_B / 32);               // (625, 2)

    gnn_transpose_kernel<<<tg, tb>>>(x);

    const long long threads = (long long)num_edges * 16;
    const int block = 256;
    const int grid  = (int)((threads + block - 1) / block);
    gnn_edge_kernel<<<grid, block>>>(adj, w, src, dst, num_edges);

    gnn_finalize_kernel<<<tg, tb>>>(x, self_w, bias, out);
}